// round 1
// baseline (speedup 1.0000x reference)
#include <cuda_runtime.h>
#include <math.h>

// ---------------- problem constants ----------------
#define BZ   2
#define SQ   2048
#define HIDN 1024
#define NHD  16
#define HDIM 64
#define MROWS (BZ * SQ)      // 4096
#define WIN  64              // LOCAL_WINDOW / 2

// ---------------- scratch (no allocations allowed) ----------------
__device__ float g_Q[MROWS * HIDN];
__device__ float g_K[MROWS * HIDN];
__device__ float g_V[MROWS * HIDN];
__device__ float g_O[MROWS * HIDN];

// ---------------- fp32 SGEMM: C[m,n] = sum_k A[m,k] * W[n,k] + bias[n] ----------------
// BM=128, BN=128, BK=8, TM=TN=8, 256 threads.
__global__ __launch_bounds__(256) void sgemm_bias_kernel(
    const float* __restrict__ A, const float* __restrict__ W,
    const float* __restrict__ bias, float* __restrict__ C,
    int Mdim, int Ndim, int Kdim)
{
    constexpr int BM = 128, BN = 128, BK = 8, TM = 8, TN = 8;
    __shared__ float As[BK][BM];
    __shared__ float Bs[BK][BN];

    const int tid = threadIdx.x;
    const int tx = tid & 15;        // 0..15 -> N
    const int ty = tid >> 4;        // 0..15 -> M
    const int mBase = blockIdx.y * BM;
    const int nBase = blockIdx.x * BN;

    // load mapping: 256 threads cover 128 rows x 8 cols via one float4 each
    const int lrow = tid >> 1;          // 0..127
    const int lc4  = (tid & 1) * 4;     // 0 or 4

    float acc[TM][TN] = {};

    for (int k0 = 0; k0 < Kdim; k0 += BK) {
        float4 a = *reinterpret_cast<const float4*>(&A[(size_t)(mBase + lrow) * Kdim + k0 + lc4]);
        float4 w = *reinterpret_cast<const float4*>(&W[(size_t)(nBase + lrow) * Kdim + k0 + lc4]);
        As[lc4 + 0][lrow] = a.x; As[lc4 + 1][lrow] = a.y;
        As[lc4 + 2][lrow] = a.z; As[lc4 + 3][lrow] = a.w;
        Bs[lc4 + 0][lrow] = w.x; Bs[lc4 + 1][lrow] = w.y;
        Bs[lc4 + 2][lrow] = w.z; Bs[lc4 + 3][lrow] = w.w;
        __syncthreads();

        #pragma unroll
        for (int k = 0; k < BK; ++k) {
            float ra[TM], rb[TN];
            #pragma unroll
            for (int i = 0; i < TM; ++i) ra[i] = As[k][ty * TM + i];
            #pragma unroll
            for (int j = 0; j < TN; ++j) rb[j] = Bs[k][tx * TN + j];
            #pragma unroll
            for (int i = 0; i < TM; ++i)
                #pragma unroll
                for (int j = 0; j < TN; ++j)
                    acc[i][j] = fmaf(ra[i], rb[j], acc[i][j]);
        }
        __syncthreads();
    }

    #pragma unroll
    for (int i = 0; i < TM; ++i) {
        const int m = mBase + ty * TM + i;
        #pragma unroll
        for (int j = 0; j < TN; ++j) {
            const int n = nBase + tx * TN + j;
            C[(size_t)m * Ndim + n] = acc[i][j] + bias[n];
        }
    }
}

// ---------------- sparse causal attention ----------------
// One CTA per (b, h, i). Keys: {0} U [max(0,i-64), i], nk <= 66.
// Q/K/V layout: [b, s, h*HD + d] i.e. row (b*S+s), col h*64+d.
#define MAXK 66
#define TPAD 65   // padded row stride to avoid bank conflicts

__global__ __launch_bounds__(128) void sparse_attn_kernel(
    const float* __restrict__ Q, const float* __restrict__ K,
    const float* __restrict__ V, float* __restrict__ O)
{
    const int i = blockIdx.x;
    const int h = blockIdx.y;
    const int b = blockIdx.z;
    const int tid = threadIdx.x;

    const int lo   = (i > WIN) ? (i - WIN) : 0;
    const int hasG = (lo > 0) ? 1 : 0;
    const int nk   = (i - lo + 1) + hasG;     // <= 66

    __shared__ float qs[HDIM];
    __shared__ float tile[MAXK * TPAD];
    __shared__ float sc[MAXK];
    __shared__ float s_inv;

    const size_t qoff = (size_t)(b * SQ + i) * HIDN + h * HDIM;
    if (tid < HDIM) qs[tid] = Q[qoff + tid];

    const size_t base = (size_t)b * SQ * HIDN + h * HDIM;

    // --- load K tile (coalesced 64-float rows) ---
    for (int idx = tid; idx < nk * HDIM; idx += 128) {
        const int r = idx >> 6;
        const int d = idx & 63;
        const int j = (hasG && r == 0) ? 0 : (lo + r - hasG);
        tile[r * TPAD + d] = K[base + (size_t)j * HIDN + d];
    }
    __syncthreads();

    // --- scores: one thread per key ---
    if (tid < nk) {
        float dot = 0.f;
        #pragma unroll
        for (int d = 0; d < HDIM; ++d)
            dot = fmaf(qs[d], tile[tid * TPAD + d], dot);
        sc[tid] = dot * 0.125f;   // 1/sqrt(64)
    }
    __syncthreads();

    // --- softmax (tiny: nk <= 66) by thread 0; others start V load ---
    if (tid == 0) {
        float m = -1e30f;
        for (int j = 0; j < nk; ++j) m = fmaxf(m, sc[j]);
        float s = 0.f;
        for (int j = 0; j < nk; ++j) { float e = expf(sc[j] - m); sc[j] = e; s += e; }
        s_inv = 1.f / s;
    }

    // --- load V tile (reuses tile buffer; safe: scores already consumed) ---
    for (int idx = tid; idx < nk * HDIM; idx += 128) {
        const int r = idx >> 6;
        const int d = idx & 63;
        const int j = (hasG && r == 0) ? 0 : (lo + r - hasG);
        tile[r * TPAD + d] = V[base + (size_t)j * HIDN + d];
    }
    __syncthreads();

    // --- output: one thread per head dim ---
    if (tid < HDIM) {
        float acc = 0.f;
        for (int j = 0; j < nk; ++j)
            acc = fmaf(sc[j], tile[j * TPAD + tid], acc);
        O[qoff + tid] = acc * s_inv;
    }
}

// ---------------- launch ----------------
extern "C" void kernel_launch(void* const* d_in, const int* in_sizes, int n_in,
                              void* d_out, int out_size)
{
    const float* X  = (const float*)d_in[0];
    const float* Wq = (const float*)d_in[1];
    const float* bq = (const float*)d_in[2];
    const float* Wk = (const float*)d_in[3];
    const float* bk = (const float*)d_in[4];
    const float* Wv = (const float*)d_in[5];
    const float* bv = (const float*)d_in[6];
    const float* Wo = (const float*)d_in[7];
    const float* bo = (const float*)d_in[8];
    float* out = (float*)d_out;

    float *Q, *K, *V, *O;
    cudaGetSymbolAddress((void**)&Q, g_Q);
    cudaGetSymbolAddress((void**)&K, g_K);
    cudaGetSymbolAddress((void**)&V, g_V);
    cudaGetSymbolAddress((void**)&O, g_O);

    const dim3 gemmGrid(HIDN / 128, MROWS / 128);  // (8, 32)
    sgemm_bias_kernel<<<gemmGrid, 256>>>(X, Wq, bq, Q, MROWS, HIDN, HIDN);
    sgemm_bias_kernel<<<gemmGrid, 256>>>(X, Wk, bk, K, MROWS, HIDN, HIDN);
    sgemm_bias_kernel<<<gemmGrid, 256>>>(X, Wv, bv, V, MROWS, HIDN, HIDN);

    const dim3 attnGrid(SQ, NHD, BZ);              // 2048 x 16 x 2
    sparse_attn_kernel<<<attnGrid, 128>>>(Q, K, V, O);

    sgemm_bias_kernel<<<gemmGrid, 256>>>(O, Wo, bo, out, MROWS, HIDN, HIDN);
}

// round 4
// speedup vs baseline: 2.4029x; 2.4029x over previous
#include <cuda_runtime.h>
#include <cuda_bf16.h>
#include <cstdint>
#include <math.h>

// ---------------- problem constants ----------------
#define BZ   2
#define SQ   2048
#define HIDN 1024
#define NHD  16
#define HDIM 64
#define MROWS (BZ * SQ)      // 4096
#define WIN  64              // LOCAL_WINDOW / 2

// ---------------- scratch (no allocations allowed) ----------------
__device__ float g_Q[MROWS * HIDN];
__device__ float g_K[MROWS * HIDN];
__device__ float g_V[MROWS * HIDN];
__device__ float g_O[MROWS * HIDN];
__device__ __nv_bfloat16 g_Xh[MROWS * HIDN];
__device__ __nv_bfloat16 g_Xl[MROWS * HIDN];
__device__ __nv_bfloat16 g_Oh[MROWS * HIDN];
__device__ __nv_bfloat16 g_Ol[MROWS * HIDN];
__device__ __nv_bfloat16 g_Wh[4][HIDN * HIDN];
__device__ __nv_bfloat16 g_Wl[4][HIDN * HIDN];

// ================= helpers =================
__device__ __forceinline__ uint32_t smem_u32(const void* p) {
    uint32_t a;
    asm("{ .reg .u64 t; cvta.to.shared.u64 t, %1; cvt.u32.u64 %0, t; }" : "=r"(a) : "l"(p));
    return a;
}
#define CP_ASYNC16(sm, gm) \
    asm volatile("cp.async.cg.shared.global [%0], [%1], 16;" :: "r"(sm), "l"(gm) : "memory")
#define CP_COMMIT() asm volatile("cp.async.commit_group;" ::: "memory")
#define CP_WAIT1()  asm volatile("cp.async.wait_group 1;" ::: "memory")
#define CP_WAIT0()  asm volatile("cp.async.wait_group 0;" ::: "memory")

#define LDSM_X4(r0, r1, r2, r3, addr) \
    asm volatile("ldmatrix.sync.aligned.m8n8.x4.shared.b16 {%0,%1,%2,%3}, [%4];" \
        : "=r"(r0), "=r"(r1), "=r"(r2), "=r"(r3) : "r"(addr))

#define MMA_BF16(d, a, b) \
    asm volatile("mma.sync.aligned.m16n8k16.row.col.f32.bf16.bf16.f32 " \
        "{%0,%1,%2,%3}, {%4,%5,%6,%7}, {%8,%9}, {%0,%1,%2,%3};" \
        : "+f"((d)[0]), "+f"((d)[1]), "+f"((d)[2]), "+f"((d)[3]) \
        : "r"((a)[0]), "r"((a)[1]), "r"((a)[2]), "r"((a)[3]), "r"((b)[0]), "r"((b)[1]))

// ================= fp32 -> (bf16 hi, bf16 lo) split =================
__global__ __launch_bounds__(256) void split_kernel(const float* __restrict__ src,
                                                    __nv_bfloat16* __restrict__ hi,
                                                    __nv_bfloat16* __restrict__ lo, int n4) {
    int i = blockIdx.x * 256 + threadIdx.x;
    if (i >= n4) return;
    float4 v = reinterpret_cast<const float4*>(src)[i];
    __nv_bfloat16 h0 = __float2bfloat16(v.x), h1 = __float2bfloat16(v.y);
    __nv_bfloat16 h2 = __float2bfloat16(v.z), h3 = __float2bfloat16(v.w);
    __nv_bfloat16 l0 = __float2bfloat16(v.x - __bfloat162float(h0));
    __nv_bfloat16 l1 = __float2bfloat16(v.y - __bfloat162float(h1));
    __nv_bfloat16 l2 = __float2bfloat16(v.z - __bfloat162float(h2));
    __nv_bfloat16 l3 = __float2bfloat16(v.w - __bfloat162float(h3));
    __nv_bfloat162 hA = __halves2bfloat162(h0, h1), hB = __halves2bfloat162(h2, h3);
    __nv_bfloat162 lA = __halves2bfloat162(l0, l1), lB = __halves2bfloat162(l2, l3);
    uint2 ho, lout;
    ho.x = *reinterpret_cast<uint32_t*>(&hA); ho.y = *reinterpret_cast<uint32_t*>(&hB);
    lout.x = *reinterpret_cast<uint32_t*>(&lA); lout.y = *reinterpret_cast<uint32_t*>(&lB);
    reinterpret_cast<uint2*>(hi)[i] = ho;
    reinterpret_cast<uint2*>(lo)[i] = lout;
}

// ================= mma.sync bf16x3 GEMM =================
// C[m,n] = sum_k A[m,k]*W[n,k] + bias[n], 3-term bf16 split.
// CTA 128x128, BK=32, 8 warps (4x2), warp tile 32x64, double-buffered cp.async.
#define GPITCH   40           // bf16 per smem row (80 B) -> conflict-free ldmatrix
#define GBUFB    10240u       // bytes per buffer: 128 * 80
#define GSTAGES  96           // 3 terms * (1024/32)

__global__ __launch_bounds__(256) void gemm_mma_kernel(
    const __nv_bfloat16* __restrict__ Ah, const __nv_bfloat16* __restrict__ Al,
    const __nv_bfloat16* __restrict__ Bh, const __nv_bfloat16* __restrict__ Bl,
    const float* __restrict__ bias, float* __restrict__ C)
{
    __shared__ __align__(16) __nv_bfloat16 sA[2][128 * GPITCH];
    __shared__ __align__(16) __nv_bfloat16 sB[2][128 * GPITCH];

    const int tid = threadIdx.x;
    const int wid = tid >> 5;
    const int lane = tid & 31;
    const int wm = wid & 3;          // warp row 0..3  (32 rows each)
    const int wn = wid >> 2;         // warp col 0..1  (64 cols each)
    const int m0 = blockIdx.y * 128;
    const int n0 = blockIdx.x * 128;

    const uint32_t saAddr = smem_u32(&sA[0][0]);
    const uint32_t sbAddr = smem_u32(&sB[0][0]);

    const int lrow = tid >> 2;       // 0..63  (row within half-tile)
    const int lchk = tid & 3;        // 16B chunk within row

    float acc[2][8][4];
    #pragma unroll
    for (int mi = 0; mi < 2; ++mi)
        #pragma unroll
        for (int j = 0; j < 8; ++j)
            #pragma unroll
            for (int r = 0; r < 4; ++r) acc[mi][j][r] = 0.f;

    auto issue_stage = [&](int s) {
        const int term = s >> 5;
        const int kk = (s & 31) << 5;        // k offset in bf16 elems
        const __nv_bfloat16* Ag = (term == 1) ? Al : Ah;
        const __nv_bfloat16* Bg = (term == 2) ? Bl : Bh;
        const uint32_t boff = (uint32_t)(s & 1) * GBUFB;
        #pragma unroll
        for (int u = 0; u < 2; ++u) {
            const int r = u * 64 + lrow;
            const uint32_t so = boff + (uint32_t)(r * 80 + lchk * 16);
            CP_ASYNC16(saAddr + so, Ag + (size_t)(m0 + r) * HIDN + kk + lchk * 8);
            CP_ASYNC16(sbAddr + so, Bg + (size_t)(n0 + r) * HIDN + kk + lchk * 8);
        }
        CP_COMMIT();
    };

    issue_stage(0);

    // fragment load base addresses (byte offsets within a buffer)
    const uint32_t aFragOff = (uint32_t)((wm * 32 + (lane & 15)) * 80 + ((lane >> 4) & 1) * 16);
    const uint32_t bFragOff = (uint32_t)((wn * 64 + (lane & 7) + ((lane >> 1) & 8)) * 80
                                         + ((lane & 8) ? 16 : 0));

    for (int s = 0; s < GSTAGES; ++s) {
        if (s + 1 < GSTAGES) { issue_stage(s + 1); CP_WAIT1(); }
        else                 { CP_WAIT0(); }
        __syncthreads();

        const uint32_t boff = (uint32_t)(s & 1) * GBUFB;
        const uint32_t aB = saAddr + boff + aFragOff;
        const uint32_t bB = sbAddr + boff + bFragOff;

        #pragma unroll
        for (int ks = 0; ks < 2; ++ks) {
            uint32_t af[2][4];
            LDSM_X4(af[0][0], af[0][1], af[0][2], af[0][3], aB + ks * 32);
            LDSM_X4(af[1][0], af[1][1], af[1][2], af[1][3], aB + 16 * 80 + ks * 32);
            uint32_t bf[8][2];
            #pragma unroll
            for (int jp = 0; jp < 4; ++jp)
                LDSM_X4(bf[2 * jp][0], bf[2 * jp][1], bf[2 * jp + 1][0], bf[2 * jp + 1][1],
                        bB + jp * 16 * 80 + ks * 32);
            #pragma unroll
            for (int mi = 0; mi < 2; ++mi)
                #pragma unroll
                for (int j = 0; j < 8; ++j)
                    MMA_BF16(acc[mi][j], af[mi], bf[j]);
        }
        __syncthreads();
    }

    // ---- epilogue ----
    const int g = lane >> 2, t = lane & 3;
    float2 bv[8];
    #pragma unroll
    for (int j = 0; j < 8; ++j) {
        const int col = n0 + wn * 64 + j * 8 + t * 2;
        bv[j].x = __ldg(bias + col);
        bv[j].y = __ldg(bias + col + 1);
    }
    #pragma unroll
    for (int mi = 0; mi < 2; ++mi) {
        const int row0 = m0 + wm * 32 + mi * 16 + g;
        #pragma unroll
        for (int j = 0; j < 8; ++j) {
            const int col = n0 + wn * 64 + j * 8 + t * 2;
            float2 o0 = { acc[mi][j][0] + bv[j].x, acc[mi][j][1] + bv[j].y };
            float2 o1 = { acc[mi][j][2] + bv[j].x, acc[mi][j][3] + bv[j].y };
            *reinterpret_cast<float2*>(C + (size_t)row0 * HIDN + col) = o0;
            *reinterpret_cast<float2*>(C + (size_t)(row0 + 8) * HIDN + col) = o1;
        }
    }
}

// ================= query-block sparse attention =================
#define KT_STRIDE 68
#define SC_STRIDE 67
#define NS_MAX 66   // uniform trip count: max keys per query (65 window + 1 global)

__global__ __launch_bounds__(256) void attn_blk_kernel(
    const float* __restrict__ Q, const float* __restrict__ K,
    const float* __restrict__ V, float* __restrict__ O)
{
    extern __shared__ float sm[];
    float* Kt   = sm;                              // [131][68]
    float* Sc   = sm + 131 * KT_STRIDE;            // [64][67]
    float* Sinv = Sc + 64 * SC_STRIDE;             // [64]

    const int qb = blockIdx.x, h = blockIdx.y, b = blockIdx.z;
    const int i0 = qb * 64;
    const int jlo = (i0 > 64) ? (i0 - 64) : 0;
    const int nrows = i0 + 63 - jlo + 1;           // 64 or 128
    const bool extraG = (jlo > 0);
    const int tid = threadIdx.x;
    const size_t base = (size_t)b * SQ * HIDN + (size_t)h * HDIM;

    // ---- load K tile ----
    for (int idx = tid; idx < nrows * 16; idx += 256) {
        int r = idx >> 4, c = idx & 15;
        float4 v = *reinterpret_cast<const float4*>(K + base + (size_t)(jlo + r) * HIDN + c * 4);
        *reinterpret_cast<float4*>(Kt + r * KT_STRIDE + c * 4) = v;
    }
    if (extraG && tid < 16) {
        float4 v = *reinterpret_cast<const float4*>(K + base + tid * 4);
        *reinterpret_cast<float4*>(Kt + 130 * KT_STRIDE + tid * 4) = v;
    }

    const int q = tid >> 2, part = tid & 3, d0 = part * 16;
    const int i = i0 + q;
    float qr[16];
    {
        const float* qp = Q + base + (size_t)i * HIDN + d0;
        #pragma unroll
        for (int d = 0; d < 16; d += 4) {
            float4 v = *reinterpret_cast<const float4*>(qp + d);
            qr[d] = v.x; qr[d + 1] = v.y; qr[d + 2] = v.z; qr[d + 3] = v.w;
        }
    }
    __syncthreads();

    const int wlo = (i > 64) ? (i - 64) : 0;
    const int r0 = wlo - jlo;
    const int nwin = i - wlo + 1;
    const bool needG = (wlo > 0);
    const int grow = extraG ? 130 : 0;
    const int ns = nwin + (needG ? 1 : 0);

    // ---- scores: 4 threads per query; UNIFORM trip count so shuffles stay convergent ----
    for (int s = 0; s < NS_MAX; ++s) {
        int row = (s < nwin) ? (r0 + s) : grow;    // dead iterations read a valid row
        const float* kp = Kt + row * KT_STRIDE + d0;
        float acc = 0.f;
        #pragma unroll
        for (int d = 0; d < 16; d += 4) {
            float4 kv = *reinterpret_cast<const float4*>(kp + d);
            acc = fmaf(qr[d], kv.x, acc); acc = fmaf(qr[d + 1], kv.y, acc);
            acc = fmaf(qr[d + 2], kv.z, acc); acc = fmaf(qr[d + 3], kv.w, acc);
        }
        acc += __shfl_xor_sync(0xffffffffu, acc, 1);
        acc += __shfl_xor_sync(0xffffffffu, acc, 2);
        if (part == 0 && s < ns) Sc[q * SC_STRIDE + s] = acc * 0.125f;
    }
    __syncthreads();   // scores done, Kt reads done

    // ---- load V tile (overwrites Kt) ----
    for (int idx = tid; idx < nrows * 16; idx += 256) {
        int r = idx >> 4, c = idx & 15;
        float4 v = *reinterpret_cast<const float4*>(V + base + (size_t)(jlo + r) * HIDN + c * 4);
        *reinterpret_cast<float4*>(Kt + r * KT_STRIDE + c * 4) = v;
    }
    if (extraG && tid < 16) {
        float4 v = *reinterpret_cast<const float4*>(V + base + tid * 4);
        *reinterpret_cast<float4*>(Kt + 130 * KT_STRIDE + tid * 4) = v;
    }

    // ---- softmax (one thread per query; no warp intrinsics -> divergence OK) ----
    if (tid < 64) {
        const int iq = i0 + tid;
        const int wloq = (iq > 64) ? (iq - 64) : 0;
        const int nwq = iq - wloq + 1;
        const int nsq = nwq + ((wloq > 0) ? 1 : 0);
        float* sc = Sc + tid * SC_STRIDE;
        float m = -1e30f;
        for (int s = 0; s < nsq; ++s) m = fmaxf(m, sc[s]);
        float sum = 0.f;
        for (int s = 0; s < nsq; ++s) { float e = __expf(sc[s] - m); sc[s] = e; sum += e; }
        Sinv[tid] = 1.f / sum;
    }
    __syncthreads();

    // ---- output (no warp intrinsics; per-thread ns is fine) ----
    float acc[16];
    #pragma unroll
    for (int d = 0; d < 16; ++d) acc[d] = 0.f;
    for (int s = 0; s < ns; ++s) {
        int row = (s < nwin) ? (r0 + s) : grow;
        float pr = Sc[q * SC_STRIDE + s];
        const float* vp = Kt + row * KT_STRIDE + d0;
        #pragma unroll
        for (int d = 0; d < 16; d += 4) {
            float4 v = *reinterpret_cast<const float4*>(vp + d);
            acc[d] = fmaf(pr, v.x, acc[d]); acc[d + 1] = fmaf(pr, v.y, acc[d + 1]);
            acc[d + 2] = fmaf(pr, v.z, acc[d + 2]); acc[d + 3] = fmaf(pr, v.w, acc[d + 3]);
        }
    }
    const float si = Sinv[q];
    float* op = O + base + (size_t)i * HIDN + d0;
    #pragma unroll
    for (int d = 0; d < 16; d += 4) {
        float4 o = { acc[d] * si, acc[d + 1] * si, acc[d + 2] * si, acc[d + 3] * si };
        *reinterpret_cast<float4*>(op + d) = o;
    }
}

// ================= launch =================
extern "C" void kernel_launch(void* const* d_in, const int* in_sizes, int n_in,
                              void* d_out, int out_size)
{
    const float* X  = (const float*)d_in[0];
    const float* Wq = (const float*)d_in[1];
    const float* bq = (const float*)d_in[2];
    const float* Wk = (const float*)d_in[3];
    const float* bk = (const float*)d_in[4];
    const float* Wv = (const float*)d_in[5];
    const float* bv = (const float*)d_in[6];
    const float* Wo = (const float*)d_in[7];
    const float* bo = (const float*)d_in[8];
    float* out = (float*)d_out;

    float *Q, *K, *V, *O;
    __nv_bfloat16 *Xh, *Xl, *Oh, *Ol, *Wh, *Wl;
    cudaGetSymbolAddress((void**)&Q, g_Q);
    cudaGetSymbolAddress((void**)&K, g_K);
    cudaGetSymbolAddress((void**)&V, g_V);
    cudaGetSymbolAddress((void**)&O, g_O);
    cudaGetSymbolAddress((void**)&Xh, g_Xh);
    cudaGetSymbolAddress((void**)&Xl, g_Xl);
    cudaGetSymbolAddress((void**)&Oh, g_Oh);
    cudaGetSymbolAddress((void**)&Ol, g_Ol);
    cudaGetSymbolAddress((void**)&Wh, g_Wh);
    cudaGetSymbolAddress((void**)&Wl, g_Wl);

    const int attn_smem = (131 * KT_STRIDE + 64 * SC_STRIDE + 64) * (int)sizeof(float);
    cudaFuncSetAttribute(attn_blk_kernel, cudaFuncAttributeMaxDynamicSharedMemorySize, attn_smem);

    const int nX4 = MROWS * HIDN / 4;
    const int nW4 = HIDN * HIDN / 4;
    split_kernel<<<nX4 / 256, 256>>>(X,  Xh, Xl, nX4);
    split_kernel<<<nW4 / 256, 256>>>(Wq, Wh + 0 * (size_t)HIDN * HIDN, Wl + 0 * (size_t)HIDN * HIDN, nW4);
    split_kernel<<<nW4 / 256, 256>>>(Wk, Wh + 1 * (size_t)HIDN * HIDN, Wl + 1 * (size_t)HIDN * HIDN, nW4);
    split_kernel<<<nW4 / 256, 256>>>(Wv, Wh + 2 * (size_t)HIDN * HIDN, Wl + 2 * (size_t)HIDN * HIDN, nW4);
    split_kernel<<<nW4 / 256, 256>>>(Wo, Wh + 3 * (size_t)HIDN * HIDN, Wl + 3 * (size_t)HIDN * HIDN, nW4);

    const dim3 gemmGrid(HIDN / 128, MROWS / 128);   // (8, 32)
    gemm_mma_kernel<<<gemmGrid, 256>>>(Xh, Xl, Wh + 0 * (size_t)HIDN * HIDN, Wl + 0 * (size_t)HIDN * HIDN, bq, Q);
    gemm_mma_kernel<<<gemmGrid, 256>>>(Xh, Xl, Wh + 1 * (size_t)HIDN * HIDN, Wl + 1 * (size_t)HIDN * HIDN, bk, K);
    gemm_mma_kernel<<<gemmGrid, 256>>>(Xh, Xl, Wh + 2 * (size_t)HIDN * HIDN, Wl + 2 * (size_t)HIDN * HIDN, bv, V);

    const dim3 attnGrid(SQ / 64, NHD, BZ);          // (32, 16, 2)
    attn_blk_kernel<<<attnGrid, 256, attn_smem>>>(Q, K, V, O);

    split_kernel<<<nX4 / 256, 256>>>(O, Oh, Ol, nX4);
    gemm_mma_kernel<<<gemmGrid, 256>>>(Oh, Ol, Wh + 3 * (size_t)HIDN * HIDN, Wl + 3 * (size_t)HIDN * HIDN, bo, out);
}

// round 5
// speedup vs baseline: 2.6147x; 1.0881x over previous
#include <cuda_runtime.h>
#include <cuda_bf16.h>
#include <cstdint>
#include <math.h>

// ---------------- problem constants ----------------
#define BZ   2
#define SQ   2048
#define HIDN 1024
#define NHD  16
#define HDIM 64
#define MROWS (BZ * SQ)      // 4096
#define WIN  64              // LOCAL_WINDOW / 2

// ---------------- scratch (no allocations allowed) ----------------
__device__ float g_Q[MROWS * HIDN];
__device__ float g_K[MROWS * HIDN];
__device__ float g_V[MROWS * HIDN];
__device__ float g_O[MROWS * HIDN];
__device__ __nv_bfloat16 g_Xh[MROWS * HIDN];
__device__ __nv_bfloat16 g_Xl[MROWS * HIDN];
__device__ __nv_bfloat16 g_Oh[MROWS * HIDN];
__device__ __nv_bfloat16 g_Ol[MROWS * HIDN];
__device__ __nv_bfloat16 g_Wh[4][HIDN * HIDN];
__device__ __nv_bfloat16 g_Wl[4][HIDN * HIDN];

// ================= helpers =================
__device__ __forceinline__ uint32_t smem_u32(const void* p) {
    uint32_t a;
    asm("{ .reg .u64 t; cvta.to.shared.u64 t, %1; cvt.u32.u64 %0, t; }" : "=r"(a) : "l"(p));
    return a;
}
#define CP_ASYNC16(sm, gm) \
    asm volatile("cp.async.cg.shared.global [%0], [%1], 16;" :: "r"(sm), "l"(gm) : "memory")
#define CP_COMMIT() asm volatile("cp.async.commit_group;" ::: "memory")
#define CP_WAIT2()  asm volatile("cp.async.wait_group 2;" ::: "memory")

#define LDSM_X4(r0, r1, r2, r3, addr) \
    asm volatile("ldmatrix.sync.aligned.m8n8.x4.shared.b16 {%0,%1,%2,%3}, [%4];" \
        : "=r"(r0), "=r"(r1), "=r"(r2), "=r"(r3) : "r"(addr))

#define MMA_BF16(d, a, b) \
    asm volatile("mma.sync.aligned.m16n8k16.row.col.f32.bf16.bf16.f32 " \
        "{%0,%1,%2,%3}, {%4,%5,%6,%7}, {%8,%9}, {%0,%1,%2,%3};" \
        : "+f"((d)[0]), "+f"((d)[1]), "+f"((d)[2]), "+f"((d)[3]) \
        : "r"((a)[0]), "r"((a)[1]), "r"((a)[2]), "r"((a)[3]), "r"((b)[0]), "r"((b)[1]))

// ================= fp32 -> (bf16 hi, bf16 lo) split =================
__global__ __launch_bounds__(256) void split_kernel(const float* __restrict__ src,
                                                    __nv_bfloat16* __restrict__ hi,
                                                    __nv_bfloat16* __restrict__ lo, int n4) {
    int i = blockIdx.x * 256 + threadIdx.x;
    if (i >= n4) return;
    float4 v = reinterpret_cast<const float4*>(src)[i];
    __nv_bfloat16 h0 = __float2bfloat16(v.x), h1 = __float2bfloat16(v.y);
    __nv_bfloat16 h2 = __float2bfloat16(v.z), h3 = __float2bfloat16(v.w);
    __nv_bfloat16 l0 = __float2bfloat16(v.x - __bfloat162float(h0));
    __nv_bfloat16 l1 = __float2bfloat16(v.y - __bfloat162float(h1));
    __nv_bfloat16 l2 = __float2bfloat16(v.z - __bfloat162float(h2));
    __nv_bfloat16 l3 = __float2bfloat16(v.w - __bfloat162float(h3));
    __nv_bfloat162 hA = __halves2bfloat162(h0, h1), hB = __halves2bfloat162(h2, h3);
    __nv_bfloat162 lA = __halves2bfloat162(l0, l1), lB = __halves2bfloat162(l2, l3);
    uint2 ho, lout;
    ho.x = *reinterpret_cast<uint32_t*>(&hA); ho.y = *reinterpret_cast<uint32_t*>(&hB);
    lout.x = *reinterpret_cast<uint32_t*>(&lA); lout.y = *reinterpret_cast<uint32_t*>(&lB);
    reinterpret_cast<uint2*>(hi)[i] = ho;
    reinterpret_cast<uint2*>(lo)[i] = lout;
}

// ================= mma.sync bf16x3 GEMM, 4-stage cp.async ring =================
// C[m,n] = sum_k A[m,k]*W[n,k] + bias[n], 3-term bf16 split.
// CTA 128x128, BK=32, 8 warps (4x2), warp tile 32x64.
#define GPITCH_B 80u          // bytes per smem row (64B data + pad) -> conflict-free ldmatrix
#define GBUFB    10240u       // bytes per matrix per stage: 128 * 80
#define GSTGB    20480u       // bytes per stage (A + B)
#define NSTAGE   4
#define GSTAGES  96           // 3 terms * (1024/32)
#define GEMM_SMEM (NSTAGE * GSTGB)   // 81920

__global__ __launch_bounds__(256, 2) void gemm_mma_kernel(
    const __nv_bfloat16* __restrict__ Ah, const __nv_bfloat16* __restrict__ Al,
    const __nv_bfloat16* __restrict__ Bh, const __nv_bfloat16* __restrict__ Bl,
    const float* __restrict__ bias, float* __restrict__ C)
{
    extern __shared__ __align__(16) char gsm[];

    const int tid = threadIdx.x;
    const int wid = tid >> 5;
    const int lane = tid & 31;
    const int wm = wid & 3;          // warp row 0..3  (32 rows each)
    const int wn = wid >> 2;         // warp col 0..1  (64 cols each)
    const int m0 = blockIdx.y * 128;
    const int n0 = blockIdx.x * 128;

    const uint32_t smBase = smem_u32(gsm);

    const int lrow = tid >> 2;       // 0..63  (row within half-tile)
    const int lchk = tid & 3;        // 16B chunk within row

    float acc[2][8][4];
    #pragma unroll
    for (int mi = 0; mi < 2; ++mi)
        #pragma unroll
        for (int j = 0; j < 8; ++j)
            #pragma unroll
            for (int r = 0; r < 4; ++r) acc[mi][j][r] = 0.f;

    auto issue_stage = [&](int s) {
        const int term = s >> 5;
        const int kk = (s & 31) << 5;        // k offset in bf16 elems
        const __nv_bfloat16* Ag = (term == 1) ? Al : Ah;
        const __nv_bfloat16* Bg = (term == 2) ? Bl : Bh;
        const uint32_t sbase = smBase + (uint32_t)(s & (NSTAGE - 1)) * GSTGB;
        #pragma unroll
        for (int u = 0; u < 2; ++u) {
            const int r = u * 64 + lrow;
            const uint32_t so = (uint32_t)r * GPITCH_B + (uint32_t)lchk * 16u;
            CP_ASYNC16(sbase + so, Ag + (size_t)(m0 + r) * HIDN + kk + lchk * 8);
            CP_ASYNC16(sbase + GBUFB + so, Bg + (size_t)(n0 + r) * HIDN + kk + lchk * 8);
        }
    };

    // prologue: stages 0..2 in flight
    issue_stage(0); CP_COMMIT();
    issue_stage(1); CP_COMMIT();
    issue_stage(2); CP_COMMIT();

    // fragment byte offsets within a stage's A / B buffer
    const uint32_t aFragOff = (uint32_t)((wm * 32 + (lane & 15)) * GPITCH_B + ((lane >> 4) & 1) * 16);
    const uint32_t bFragOff = (uint32_t)((wn * 64 + (lane & 7) + ((lane >> 1) & 8)) * GPITCH_B
                                         + ((lane & 8) ? 16 : 0)) + GBUFB;

    for (int s = 0; s < GSTAGES; ++s) {
        CP_WAIT2();              // stage s data has arrived (stages s+1, s+2 may be pending)
        __syncthreads();         // also: everyone done reading buf (s-1)%4 == (s+3)%4

        if (s + 3 < GSTAGES) issue_stage(s + 3);
        CP_COMMIT();             // empty commit near tail keeps group counting valid

        const uint32_t sbase = smBase + (uint32_t)(s & (NSTAGE - 1)) * GSTGB;
        const uint32_t aB = sbase + aFragOff;
        const uint32_t bB = sbase + bFragOff;

        #pragma unroll
        for (int ks = 0; ks < 2; ++ks) {
            uint32_t af[2][4];
            LDSM_X4(af[0][0], af[0][1], af[0][2], af[0][3], aB + ks * 32);
            LDSM_X4(af[1][0], af[1][1], af[1][2], af[1][3], aB + 16 * GPITCH_B + ks * 32);
            uint32_t bf[8][2];
            #pragma unroll
            for (int jp = 0; jp < 4; ++jp)
                LDSM_X4(bf[2 * jp][0], bf[2 * jp][1], bf[2 * jp + 1][0], bf[2 * jp + 1][1],
                        bB + jp * 16 * GPITCH_B + ks * 32);
            #pragma unroll
            for (int mi = 0; mi < 2; ++mi)
                #pragma unroll
                for (int j = 0; j < 8; ++j)
                    MMA_BF16(acc[mi][j], af[mi], bf[j]);
        }
    }

    // ---- epilogue ----
    const int g = lane >> 2, t = lane & 3;
    float2 bv[8];
    #pragma unroll
    for (int j = 0; j < 8; ++j) {
        const int col = n0 + wn * 64 + j * 8 + t * 2;
        bv[j].x = __ldg(bias + col);
        bv[j].y = __ldg(bias + col + 1);
    }
    #pragma unroll
    for (int mi = 0; mi < 2; ++mi) {
        const int row0 = m0 + wm * 32 + mi * 16 + g;
        #pragma unroll
        for (int j = 0; j < 8; ++j) {
            const int col = n0 + wn * 64 + j * 8 + t * 2;
            float2 o0 = { acc[mi][j][0] + bv[j].x, acc[mi][j][1] + bv[j].y };
            float2 o1 = { acc[mi][j][2] + bv[j].x, acc[mi][j][3] + bv[j].y };
            *reinterpret_cast<float2*>(C + (size_t)row0 * HIDN + col) = o0;
            *reinterpret_cast<float2*>(C + (size_t)(row0 + 8) * HIDN + col) = o1;
        }
    }
}

// ================= query-block sparse attention =================
#define KT_STRIDE 68
#define SC_STRIDE 67
#define NS_MAX 66   // uniform trip count: max keys per query (65 window + 1 global)

__global__ __launch_bounds__(256) void attn_blk_kernel(
    const float* __restrict__ Q, const float* __restrict__ K,
    const float* __restrict__ V, float* __restrict__ O)
{
    extern __shared__ float sm[];
    float* Kt   = sm;                              // [131][68]
    float* Sc   = sm + 131 * KT_STRIDE;            // [64][67]
    float* Sinv = Sc + 64 * SC_STRIDE;             // [64]

    const int qb = blockIdx.x, h = blockIdx.y, b = blockIdx.z;
    const int i0 = qb * 64;
    const int jlo = (i0 > 64) ? (i0 - 64) : 0;
    const int nrows = i0 + 63 - jlo + 1;           // 64 or 128
    const bool extraG = (jlo > 0);
    const int tid = threadIdx.x;
    const size_t base = (size_t)b * SQ * HIDN + (size_t)h * HDIM;

    // ---- load K tile ----
    for (int idx = tid; idx < nrows * 16; idx += 256) {
        int r = idx >> 4, c = idx & 15;
        float4 v = *reinterpret_cast<const float4*>(K + base + (size_t)(jlo + r) * HIDN + c * 4);
        *reinterpret_cast<float4*>(Kt + r * KT_STRIDE + c * 4) = v;
    }
    if (extraG && tid < 16) {
        float4 v = *reinterpret_cast<const float4*>(K + base + tid * 4);
        *reinterpret_cast<float4*>(Kt + 130 * KT_STRIDE + tid * 4) = v;
    }

    const int q = tid >> 2, part = tid & 3, d0 = part * 16;
    const int i = i0 + q;
    float qr[16];
    {
        const float* qp = Q + base + (size_t)i * HIDN + d0;
        #pragma unroll
        for (int d = 0; d < 16; d += 4) {
            float4 v = *reinterpret_cast<const float4*>(qp + d);
            qr[d] = v.x; qr[d + 1] = v.y; qr[d + 2] = v.z; qr[d + 3] = v.w;
        }
    }
    __syncthreads();

    const int wlo = (i > 64) ? (i - 64) : 0;
    const int r0 = wlo - jlo;
    const int nwin = i - wlo + 1;
    const bool needG = (wlo > 0);
    const int grow = extraG ? 130 : 0;
    const int ns = nwin + (needG ? 1 : 0);

    // ---- scores: 4 threads per query; UNIFORM trip count so shuffles stay convergent ----
    for (int s = 0; s < NS_MAX; ++s) {
        int row = (s < nwin) ? (r0 + s) : grow;    // dead iterations read a valid row
        const float* kp = Kt + row * KT_STRIDE + d0;
        float acc = 0.f;
        #pragma unroll
        for (int d = 0; d < 16; d += 4) {
            float4 kv = *reinterpret_cast<const float4*>(kp + d);
            acc = fmaf(qr[d], kv.x, acc); acc = fmaf(qr[d + 1], kv.y, acc);
            acc = fmaf(qr[d + 2], kv.z, acc); acc = fmaf(qr[d + 3], kv.w, acc);
        }
        acc += __shfl_xor_sync(0xffffffffu, acc, 1);
        acc += __shfl_xor_sync(0xffffffffu, acc, 2);
        if (part == 0 && s < ns) Sc[q * SC_STRIDE + s] = acc * 0.125f;
    }
    __syncthreads();   // scores done, Kt reads done

    // ---- load V tile (overwrites Kt) ----
    for (int idx = tid; idx < nrows * 16; idx += 256) {
        int r = idx >> 4, c = idx & 15;
        float4 v = *reinterpret_cast<const float4*>(V + base + (size_t)(jlo + r) * HIDN + c * 4);
        *reinterpret_cast<float4*>(Kt + r * KT_STRIDE + c * 4) = v;
    }
    if (extraG && tid < 16) {
        float4 v = *reinterpret_cast<const float4*>(V + base + tid * 4);
        *reinterpret_cast<float4*>(Kt + 130 * KT_STRIDE + tid * 4) = v;
    }

    // ---- softmax (one thread per query) ----
    if (tid < 64) {
        const int iq = i0 + tid;
        const int wloq = (iq > 64) ? (iq - 64) : 0;
        const int nwq = iq - wloq + 1;
        const int nsq = nwq + ((wloq > 0) ? 1 : 0);
        float* sc = Sc + tid * SC_STRIDE;
        float m = -1e30f;
        for (int s = 0; s < nsq; ++s) m = fmaxf(m, sc[s]);
        float sum = 0.f;
        for (int s = 0; s < nsq; ++s) { float e = __expf(sc[s] - m); sc[s] = e; sum += e; }
        Sinv[tid] = 1.f / sum;
    }
    __syncthreads();

    // ---- output ----
    float acc[16];
    #pragma unroll
    for (int d = 0; d < 16; ++d) acc[d] = 0.f;
    for (int s = 0; s < ns; ++s) {
        int row = (s < nwin) ? (r0 + s) : grow;
        float pr = Sc[q * SC_STRIDE + s];
        const float* vp = Kt + row * KT_STRIDE + d0;
        #pragma unroll
        for (int d = 0; d < 16; d += 4) {
            float4 v = *reinterpret_cast<const float4*>(vp + d);
            acc[d] = fmaf(pr, v.x, acc[d]); acc[d + 1] = fmaf(pr, v.y, acc[d + 1]);
            acc[d + 2] = fmaf(pr, v.z, acc[d + 2]); acc[d + 3] = fmaf(pr, v.w, acc[d + 3]);
        }
    }
    const float si = Sinv[q];
    float* op = O + base + (size_t)i * HIDN + d0;
    #pragma unroll
    for (int d = 0; d < 16; d += 4) {
        float4 o = { acc[d] * si, acc[d + 1] * si, acc[d + 2] * si, acc[d + 3] * si };
        *reinterpret_cast<float4*>(op + d) = o;
    }
}

// ================= launch =================
extern "C" void kernel_launch(void* const* d_in, const int* in_sizes, int n_in,
                              void* d_out, int out_size)
{
    const float* X  = (const float*)d_in[0];
    const float* Wq = (const float*)d_in[1];
    const float* bq = (const float*)d_in[2];
    const float* Wk = (const float*)d_in[3];
    const float* bk = (const float*)d_in[4];
    const float* Wv = (const float*)d_in[5];
    const float* bv = (const float*)d_in[6];
    const float* Wo = (const float*)d_in[7];
    const float* bo = (const float*)d_in[8];
    float* out = (float*)d_out;

    float *Q, *K, *V, *O;
    __nv_bfloat16 *Xh, *Xl, *Oh, *Ol, *Wh, *Wl;
    cudaGetSymbolAddress((void**)&Q, g_Q);
    cudaGetSymbolAddress((void**)&K, g_K);
    cudaGetSymbolAddress((void**)&V, g_V);
    cudaGetSymbolAddress((void**)&O, g_O);
    cudaGetSymbolAddress((void**)&Xh, g_Xh);
    cudaGetSymbolAddress((void**)&Xl, g_Xl);
    cudaGetSymbolAddress((void**)&Oh, g_Oh);
    cudaGetSymbolAddress((void**)&Ol, g_Ol);
    cudaGetSymbolAddress((void**)&Wh, g_Wh);
    cudaGetSymbolAddress((void**)&Wl, g_Wl);

    const int attn_smem = (131 * KT_STRIDE + 64 * SC_STRIDE + 64) * (int)sizeof(float);
    cudaFuncSetAttribute(attn_blk_kernel, cudaFuncAttributeMaxDynamicSharedMemorySize, attn_smem);
    cudaFuncSetAttribute(gemm_mma_kernel, cudaFuncAttributeMaxDynamicSharedMemorySize, GEMM_SMEM);

    const int nX4 = MROWS * HIDN / 4;
    const int nW4 = HIDN * HIDN / 4;
    split_kernel<<<nX4 / 256, 256>>>(X,  Xh, Xl, nX4);
    split_kernel<<<nW4 / 256, 256>>>(Wq, Wh + 0 * (size_t)HIDN * HIDN, Wl + 0 * (size_t)HIDN * HIDN, nW4);
    split_kernel<<<nW4 / 256, 256>>>(Wk, Wh + 1 * (size_t)HIDN * HIDN, Wl + 1 * (size_t)HIDN * HIDN, nW4);
    split_kernel<<<nW4 / 256, 256>>>(Wv, Wh + 2 * (size_t)HIDN * HIDN, Wl + 2 * (size_t)HIDN * HIDN, nW4);
    split_kernel<<<nW4 / 256, 256>>>(Wo, Wh + 3 * (size_t)HIDN * HIDN, Wl + 3 * (size_t)HIDN * HIDN, nW4);

    const dim3 gemmGrid(HIDN / 128, MROWS / 128);   // (8, 32) = 256 CTAs, 2/SM resident
    gemm_mma_kernel<<<gemmGrid, 256, GEMM_SMEM>>>(Xh, Xl, Wh + 0 * (size_t)HIDN * HIDN, Wl + 0 * (size_t)HIDN * HIDN, bq, Q);
    gemm_mma_kernel<<<gemmGrid, 256, GEMM_SMEM>>>(Xh, Xl, Wh + 1 * (size_t)HIDN * HIDN, Wl + 1 * (size_t)HIDN * HIDN, bk, K);
    gemm_mma_kernel<<<gemmGrid, 256, GEMM_SMEM>>>(Xh, Xl, Wh + 2 * (size_t)HIDN * HIDN, Wl + 2 * (size_t)HIDN * HIDN, bv, V);

    const dim3 attnGrid(SQ / 64, NHD, BZ);          // (32, 16, 2)
    attn_blk_kernel<<<attnGrid, 256, attn_smem>>>(Q, K, V, O);

    split_kernel<<<nX4 / 256, 256>>>(O, Oh, Ol, nX4);
    gemm_mma_kernel<<<gemmGrid, 256, GEMM_SMEM>>>(Oh, Ol, Wh + 3 * (size_t)HIDN * HIDN, Wl + 3 * (size_t)HIDN * HIDN, bo, out);
}